// round 8
// baseline (speedup 1.0000x reference)
#include <cuda_runtime.h>
#include <cuda_bf16.h>
#include <cstdint>

// Problem constants
#define DN   128      // embedding dim
#define CN   50       // conv channels
#define RNUM 237      // relations
#define BNUM 16384    // triples
#define TPC  16       // triples per CTA
#define KCH  24       // chunks per relation (capacity 384 triples/relation)

typedef unsigned long long ull;

// ---- device scratch (no allocations allowed) ----
__device__ int g_count[RNUM];   // zero at module load; k_scan resets to 0 each run
__device__ int g_start[RNUM];
__device__ int g_cnt[RNUM];
__device__ int g_cursor[RNUM];
__device__ int g_sorted[BNUM];

// ---------------------------------------------------------------------------
// f32x2 packed helpers
// ---------------------------------------------------------------------------
__device__ __forceinline__ ull pk2(float a) {           // (a, a)
    ull r; asm("mov.b64 %0, {%1, %1};" : "=l"(r) : "f"(a)); return r;
}
__device__ __forceinline__ ull pk(float a, float b) {   // (a, b)  lo=a, hi=b
    ull r; asm("mov.b64 %0, {%1, %2};" : "=l"(r) : "f"(a), "f"(b)); return r;
}
__device__ __forceinline__ void unpk(ull v, float& lo, float& hi) {
    asm("mov.b64 {%0, %1}, %2;" : "=f"(lo), "=f"(hi) : "l"(v));
}
__device__ __forceinline__ ull ffma2(ull a, ull b, ull c) {
    ull d; asm("fma.rn.f32x2 %0, %1, %2, %3;" : "=l"(d) : "l"(a), "l"(b), "l"(c)); return d;
}
__device__ __forceinline__ ull fadd2(ull a, ull b) {
    ull d; asm("add.rn.f32x2 %0, %1, %2;" : "=l"(d) : "l"(a), "l"(b)); return d;
}

// ---------------------------------------------------------------------------
// Prep: hist -> scan(+reset) -> aggregated scatter
// ---------------------------------------------------------------------------
__global__ void k_hist(const int* __restrict__ triples) {
    __shared__ int sh[RNUM];
    for (int i = threadIdx.x; i < RNUM; i += blockDim.x) sh[i] = 0;
    __syncthreads();
    int i = blockIdx.x * blockDim.x + threadIdx.x;
    if (i < BNUM) atomicAdd(&sh[triples[3 * i + 1]], 1);
    __syncthreads();
    for (int i2 = threadIdx.x; i2 < RNUM; i2 += blockDim.x) {
        int v = sh[i2];
        if (v) atomicAdd(&g_count[i2], v);
    }
}

__global__ void k_scan() {
    // 32 threads: lane l handles bins [8l, 8l+8)
    int l = threadIdx.x;
    int vals[8];
    int cnts[8];
    int sum = 0;
#pragma unroll
    for (int j = 0; j < 8; j++) {
        int b = l * 8 + j;
        vals[j] = sum;
        cnts[j] = (b < RNUM) ? g_count[b] : 0;
        sum += cnts[j];
    }
    int x = sum;
#pragma unroll
    for (int sft = 1; sft < 32; sft <<= 1) {
        int y = __shfl_up_sync(0xffffffffu, x, sft);
        if (l >= sft) x += y;
    }
    int off = x - sum;
#pragma unroll
    for (int j = 0; j < 8; j++) {
        int b = l * 8 + j;
        if (b < RNUM) {
            int s = off + vals[j];
            g_start[b]  = s;
            g_cursor[b] = s;
            g_cnt[b]    = cnts[j];
            g_count[b]  = 0;   // reset for next replay
        }
    }
}

// 32 blocks x 512 threads, 1 element each; smem-aggregated scatter
__global__ void k_scatter(const int* __restrict__ triples) {
    __shared__ int lcnt[RNUM];
    __shared__ int lcur[RNUM];
    const int tid = threadIdx.x;
    for (int i = tid; i < RNUM; i += 512) lcnt[i] = 0;
    __syncthreads();
    const int i = blockIdx.x * 512 + tid;
    const int r = triples[3 * i + 1];
    atomicAdd(&lcnt[r], 1);
    __syncthreads();
    for (int b = tid; b < RNUM; b += 512) {
        int c = lcnt[b];
        int base = c ? atomicAdd(&g_cursor[b], c) : 0;
        lcur[b] = base;
    }
    __syncthreads();
    int pos = atomicAdd(&lcur[r], 1);
    g_sorted[pos] = i;
}

// ---------------------------------------------------------------------------
// Main kernel: one CTA = (relation r, chunk of up to 16 triples), 128 threads
//   f32x2 over (h,t) pairs in the matvec; f32x2 over col-pairs in the epilogue
// ---------------------------------------------------------------------------
#define OFF_WR   0
#define OFF_X    (DN*DN)                    // 16384
#define OFF_REL  (OFF_X + TPC*2*DN)         // 20480
#define OFF_FCH  (OFF_REL + DN)             // 20608
#define OFF_CW   (OFF_FCH + CN*DN)          // 27008
#define OFF_CB   (OFF_CW + 152)             // 27160
#define OFF_TID  (OFF_CB + 56)              // 27216 (ints)
#define SMEM_BYTES ((OFF_TID)*4 + TPC*4)

__global__ __launch_bounds__(128)
void k_main(const int* __restrict__ triples,
            const float* __restrict__ ent_emb,
            const float* __restrict__ rel_emb,
            const float* __restrict__ rel_W,
            const float* __restrict__ conv_w,
            const float* __restrict__ conv_b,
            const float* __restrict__ fc_w,
            const float* __restrict__ fc_b,
            float* __restrict__ out)
{
    const int r     = blockIdx.x / KCH;
    const int chunk = blockIdx.x % KCH;

    const int cnt  = g_cnt[r];
    const int base = chunk * TPC;
    const int n    = min(TPC, cnt - base);
    if (n <= 0) return;
    const int gbase = g_start[r] + base;

    extern __shared__ float smem[];
    float* sWr  = smem + OFF_WR;
    float* sXi  = smem + OFF_X;     // [slot][d][2] = {h_d, t_d} (256 floats/slot)
    float* sRel = smem + OFF_REL;
    float* sFch = smem + OFF_FCH;   // fc_w * 0.5
    float* sCw  = smem + OFF_CW;
    float* sCb  = smem + OFF_CB;
    int*   sTid = (int*)(smem + OFF_TID);

    const int tid = threadIdx.x;

    // ---- stage Wr (64KB, row-major [d][e]) ----
    {
        const float4* gW = (const float4*)(rel_W + (size_t)r * DN * DN);
        float4* sW4 = (float4*)sWr;
#pragma unroll 4
        for (int i = tid; i < DN * DN / 4; i += 128) sW4[i] = gW[i];
    }
    // ---- stage fc_w * 0.5 ----
    {
        const float4* gF = (const float4*)fc_w;
        float4* sF4 = (float4*)sFch;
        for (int i = tid; i < CN * DN / 4; i += 128) {
            float4 v = gF[i];
            v.x *= 0.5f; v.y *= 0.5f; v.z *= 0.5f; v.w *= 0.5f;
            sF4[i] = v;
        }
    }
    // ---- stage rel_emb[r], conv_w, conv_b ----
    if (tid < 32) ((float4*)sRel)[tid] = ((const float4*)(rel_emb + (size_t)r * DN))[tid];
    for (int i = tid; i < CN * 3; i += 128) sCw[i] = conv_w[i];
    if (tid < CN) sCb[tid] = conv_b[tid];

    // ---- stage entity rows interleaved {h,t}: 8 threads per slot ----
    {
        const int s  = tid >> 3;        // 0..15
        const int l8 = tid & 7;
        float4* sX4 = (float4*)sXi;     // slot stride = 64 float4 (256 floats)
        if (s < n) {
            int i = g_sorted[gbase + s];
            if (l8 == 0) sTid[s] = i;
            int h = triples[3 * i + 0];
            int t = triples[3 * i + 2];
            const float4* eh = (const float4*)(ent_emb + (size_t)h * DN);
            const float4* et = (const float4*)(ent_emb + (size_t)t * DN);
#pragma unroll
            for (int kk = 0; kk < 4; kk++) {
                int m = kk * 8 + l8;            // float4 index along d (d=4m..4m+3)
                float4 a = eh[m];
                float4 b = et[m];
                sX4[s * 64 + 2 * m]     = make_float4(a.x, b.x, a.y, b.y);
                sX4[s * 64 + 2 * m + 1] = make_float4(a.z, b.z, a.w, b.w);
            }
        } else {
            float4 z = make_float4(0.f, 0.f, 0.f, 0.f);
#pragma unroll
            for (int kk = 0; kk < 4; kk++) {
                int m = kk * 8 + l8;
                sX4[s * 64 + 2 * m]     = z;
                sX4[s * 64 + 2 * m + 1] = z;
            }
        }
    }
    __syncthreads();

    // ---- matvecs: warp w -> triples 4w..4w+3, lane l -> cols 4l..4l+3 ----
    const int l  = tid & 31;
    const int w  = tid >> 5;
    const int tb = w * 4;

    ull acc[4][4];   // [triple][col] packed (ph, pt)
#pragma unroll
    for (int q = 0; q < 4; q++)
#pragma unroll
        for (int j = 0; j < 4; j++) acc[q][j] = 0ULL;

    const float4*     sW4  = (const float4*)sWr;
    const ulonglong2* sX2  = (const ulonglong2*)sXi;   // slot stride = 64 ulonglong2

#pragma unroll 2
    for (int d4 = 0; d4 < DN / 4; d4++) {
        ull wd[16];
#pragma unroll
        for (int dd = 0; dd < 4; dd++) {
            float4 wr = sW4[(d4 * 4 + dd) * 32 + l];
            wd[dd * 4 + 0] = pk2(wr.x);
            wd[dd * 4 + 1] = pk2(wr.y);
            wd[dd * 4 + 2] = pk2(wr.z);
            wd[dd * 4 + 3] = pk2(wr.w);
        }
#pragma unroll
        for (int q = 0; q < 4; q++) {
            // FIX (R5 bug): slot stride is 64 ulonglong2, not 32
            ulonglong2 xa = sX2[(tb + q) * 64 + d4 * 2];      // (h0,t0),(h1,t1)
            ulonglong2 xb = sX2[(tb + q) * 64 + d4 * 2 + 1];  // (h2,t2),(h3,t3)
            ull xv0 = xa.x, xv1 = xa.y, xv2 = xb.x, xv3 = xb.y;
#pragma unroll
            for (int j = 0; j < 4; j++) {
                acc[q][j] = ffma2(xv0, wd[0 * 4 + j], acc[q][j]);
                acc[q][j] = ffma2(xv1, wd[1 * 4 + j], acc[q][j]);
                acc[q][j] = ffma2(xv2, wd[2 * 4 + j], acc[q][j]);
                acc[q][j] = ffma2(xv3, wd[3 * 4 + j], acc[q][j]);
            }
        }
    }

    // ---- unpack (ph,pt) pairs, repack over column-pairs ----
    float ph[4][4], pt[4][4];
#pragma unroll
    for (int q = 0; q < 4; q++)
#pragma unroll
        for (int j = 0; j < 4; j++) unpk(acc[q][j], ph[q][j], pt[q][j]);

    ull php[4][2], ptp[4][2];
#pragma unroll
    for (int q = 0; q < 4; q++) {
        php[q][0] = pk(ph[q][0], ph[q][1]);
        php[q][1] = pk(ph[q][2], ph[q][3]);
        ptp[q][0] = pk(pt[q][0], pt[q][1]);
        ptp[q][1] = pk(pt[q][2], pt[q][3]);
    }

    // rel pairs for this lane's 4 cols
    ulonglong2 rr2 = ((const ulonglong2*)sRel)[l];
    ull rrp0 = rr2.x, rrp1 = rr2.y;

    const ulonglong2* sF2 = (const ulonglong2*)sFch;
    const ull ABSM = 0x7FFFFFFF7FFFFFFFULL;

    ull part[4] = {0ULL, 0ULL, 0ULL, 0ULL};

#pragma unroll 2
    for (int c = 0; c < CN; c++) {
        ull c0p = pk2(sCw[3 * c + 0]);
        ull c1p = pk2(sCw[3 * c + 1]);
        ull c2p = pk2(sCw[3 * c + 2]);
        ull cbp = pk2(sCb[c]);
        // FIX (R5 bug): channel row stride is 32 ulonglong2, not 16
        ulonglong2 fw2 = sF2[c * 32 + l];
        ull fw0 = fw2.x, fw1 = fw2.y;
        // per-channel rel contribution (shared across triples)
        ull s0 = ffma2(rrp0, c1p, cbp);
        ull s1 = ffma2(rrp1, c1p, cbp);
#pragma unroll
        for (int q = 0; q < 4; q++) {
            ull g0 = ffma2(php[q][0], c0p, ffma2(ptp[q][0], c2p, s0));
            ull g1 = ffma2(php[q][1], c0p, ffma2(ptp[q][1], c2p, s1));
            // relu(g)*fw == (g + |g|) * (fw/2)
            ull v0 = fadd2(g0, g0 & ABSM);
            ull v1 = fadd2(g1, g1 & ABSM);
            part[q] = ffma2(v0, fw0, part[q]);
            part[q] = ffma2(v1, fw1, part[q]);
        }
    }

    const float fcb = __ldg(fc_b);
#pragma unroll
    for (int q = 0; q < 4; q++) {
        float lo, hi;
        unpk(part[q], lo, hi);
        float v = lo + hi;
#pragma unroll
        for (int s = 16; s; s >>= 1) v += __shfl_xor_sync(0xffffffffu, v, s);
        if (l == 0 && tb + q < n) out[sTid[tb + q]] = v + fcb;
    }
}

// ---------------------------------------------------------------------------
extern "C" void kernel_launch(void* const* d_in, const int* in_sizes, int n_in,
                              void* d_out, int out_size)
{
    const int*   triples = (const int*)d_in[0];
    const float* ent_emb = (const float*)d_in[1];
    const float* rel_emb = (const float*)d_in[2];
    const float* rel_W   = (const float*)d_in[3];
    const float* conv_w  = (const float*)d_in[4];
    const float* conv_b  = (const float*)d_in[5];
    const float* fc_w    = (const float*)d_in[6];
    const float* fc_b    = (const float*)d_in[7];
    float* out = (float*)d_out;

    cudaFuncSetAttribute(k_main, cudaFuncAttributeMaxDynamicSharedMemorySize, SMEM_BYTES);

    k_hist<<<(BNUM + 255) / 256, 256>>>(triples);
    k_scan<<<1, 32>>>();
    k_scatter<<<BNUM / 512, 512>>>(triples);
    k_main<<<RNUM * KCH, 128, SMEM_BYTES>>>(triples, ent_emb, rel_emb, rel_W,
                                            conv_w, conv_b, fc_w, fc_b, out);
}

// round 9
// speedup vs baseline: 1.6526x; 1.6526x over previous
#include <cuda_runtime.h>
#include <cuda_bf16.h>
#include <cstdint>

// Problem constants
#define DN   128      // embedding dim
#define CN   50       // conv channels
#define RNUM 237      // relations
#define BNUM 16384    // triples
#define TPC  40       // triples per CTA (10 warps x 4)
#define KCH  10       // chunks per relation (capacity 400 triples/relation)
#define NTHR 320      // 10 warps

// ---- device scratch (no allocations allowed) ----
__device__ int g_count[RNUM];   // zero at module load; k_scan resets it each run
__device__ int g_start[RNUM];
__device__ int g_cnt[RNUM];
__device__ int g_cursor[RNUM];
__device__ int g_sorted[BNUM];

// ---------------------------------------------------------------------------
// Prep: hist -> scan(+reset) -> aggregated scatter
// ---------------------------------------------------------------------------
__global__ void k_hist(const int* __restrict__ triples) {
    __shared__ int sh[RNUM];
    for (int i = threadIdx.x; i < RNUM; i += blockDim.x) sh[i] = 0;
    __syncthreads();
    int i = blockIdx.x * blockDim.x + threadIdx.x;
    if (i < BNUM) atomicAdd(&sh[triples[3 * i + 1]], 1);
    __syncthreads();
    for (int i2 = threadIdx.x; i2 < RNUM; i2 += blockDim.x) {
        int v = sh[i2];
        if (v) atomicAdd(&g_count[i2], v);
    }
}

__global__ void k_scan() {
    // 32 threads: lane l handles bins [8l, 8l+8)
    int l = threadIdx.x;
    int vals[8];
    int cnts[8];
    int sum = 0;
#pragma unroll
    for (int j = 0; j < 8; j++) {
        int b = l * 8 + j;
        vals[j] = sum;
        cnts[j] = (b < RNUM) ? g_count[b] : 0;
        sum += cnts[j];
    }
    int x = sum;
#pragma unroll
    for (int sft = 1; sft < 32; sft <<= 1) {
        int y = __shfl_up_sync(0xffffffffu, x, sft);
        if (l >= sft) x += y;
    }
    int off = x - sum;
#pragma unroll
    for (int j = 0; j < 8; j++) {
        int b = l * 8 + j;
        if (b < RNUM) {
            int s = off + vals[j];
            g_start[b]  = s;
            g_cursor[b] = s;
            g_cnt[b]    = cnts[j];
            g_count[b]  = 0;   // reset for next graph replay
        }
    }
}

// 32 blocks x 512 threads, 1 element each; smem-aggregated scatter
__global__ void k_scatter(const int* __restrict__ triples) {
    __shared__ int lcnt[RNUM];
    __shared__ int lcur[RNUM];
    const int tid = threadIdx.x;
    for (int i = tid; i < RNUM; i += 512) lcnt[i] = 0;
    __syncthreads();
    const int i = blockIdx.x * 512 + tid;
    const int r = triples[3 * i + 1];
    atomicAdd(&lcnt[r], 1);
    __syncthreads();
    for (int b = tid; b < RNUM; b += 512) {
        int c = lcnt[b];
        int base = c ? atomicAdd(&g_cursor[b], c) : 0;
        lcur[b] = base;
    }
    __syncthreads();
    int pos = atomicAdd(&lcur[r], 1);
    g_sorted[pos] = i;
}

// ---------------------------------------------------------------------------
// Main kernel: one CTA = (relation r, chunk of up to 40 triples), 320 threads
//   scalar FFMA; warp w -> triples 4w..4w+3, lane l -> output cols 4l..4l+3
//   smem: Wr 64KB + X 40KB + rel + packed conv params  (~105KB -> 2 CTAs/SM)
//   fc_w read directly from global (L2-resident, shared by all CTAs)
// ---------------------------------------------------------------------------
#define OFF_X    (DN*DN)                    // 16384
#define OFF_REL  (OFF_X + TPC*2*DN)         // 26624
#define OFF_CP   (OFF_REL + DN)             // 26752  (50 x float4)
#define OFF_TID  (OFF_CP + 4*CN)            // 26952  (ints)
#define SMEM_BYTES (OFF_TID*4 + TPC*4)

__global__ __launch_bounds__(NTHR, 2)
void k_main(const int* __restrict__ triples,
            const float* __restrict__ ent_emb,
            const float* __restrict__ rel_emb,
            const float* __restrict__ rel_W,
            const float* __restrict__ conv_w,
            const float* __restrict__ conv_b,
            const float* __restrict__ fc_w,
            const float* __restrict__ fc_b,
            float* __restrict__ out)
{
    const int r     = blockIdx.x / KCH;
    const int chunk = blockIdx.x % KCH;

    const int cnt  = g_cnt[r];
    const int base = chunk * TPC;
    const int n    = min(TPC, cnt - base);
    if (n <= 0) return;
    const int gbase = g_start[r] + base;

    extern __shared__ float smem[];
    float* sWr  = smem;                 // [d][e] row-major, 16384 floats
    float* sX   = smem + OFF_X;         // [slot][h(128)|t(128)]
    float* sRel = smem + OFF_REL;       // 128
    float* sCp  = smem + OFF_CP;        // 50 x {cw0,cw1,cw2,cb}
    int*   sTid = (int*)(smem + OFF_TID);

    const int tid = threadIdx.x;

    // ---- stage Wr (64KB) ----
    {
        const float4* gW = (const float4*)(rel_W + (size_t)r * DN * DN);
        float4* sW4 = (float4*)sWr;
#pragma unroll 4
        for (int i = tid; i < DN * DN / 4; i += NTHR) sW4[i] = gW[i];
    }
    // ---- stage rel_emb[r], packed conv params ----
    if (tid < 32) ((float4*)sRel)[tid] = ((const float4*)(rel_emb + (size_t)r * DN))[tid];
    if (tid < CN) {
        float4 cp;
        cp.x = conv_w[3 * tid + 0];
        cp.y = conv_w[3 * tid + 1];
        cp.z = conv_w[3 * tid + 2];
        cp.w = conv_b[tid];
        ((float4*)sCp)[tid] = cp;
    }

    // ---- stage entity rows: 8 threads per slot (40 slots x 8 = 320) ----
    {
        const int s  = tid >> 3;        // 0..39
        const int l8 = tid & 7;
        float4* sX4 = (float4*)sX;      // slot stride = 64 float4
        if (s < n) {
            int i = g_sorted[gbase + s];
            if (l8 == 0) sTid[s] = i;
            int h = triples[3 * i + 0];
            int t = triples[3 * i + 2];
            const float4* eh = (const float4*)(ent_emb + (size_t)h * DN);
            const float4* et = (const float4*)(ent_emb + (size_t)t * DN);
#pragma unroll
            for (int kk = 0; kk < 4; kk++) {
                int m = kk * 8 + l8;
                sX4[s * 64 + m]      = eh[m];
                sX4[s * 64 + 32 + m] = et[m];
            }
        } else {
            float4 z = make_float4(0.f, 0.f, 0.f, 0.f);
#pragma unroll
            for (int kk = 0; kk < 4; kk++) {
                int m = kk * 8 + l8;
                sX4[s * 64 + m]      = z;
                sX4[s * 64 + 32 + m] = z;
            }
        }
    }
    __syncthreads();

    // ---- matvecs: warp w -> triples 4w..4w+3, lane l -> cols 4l..4l+3 ----
    const int l  = tid & 31;
    const int w  = tid >> 5;            // 0..9
    const int tb = w * 4;

    float acc[4][8];   // [triple][0..3 = ph cols, 4..7 = pt cols]
#pragma unroll
    for (int q = 0; q < 4; q++)
#pragma unroll
        for (int j = 0; j < 8; j++) acc[q][j] = 0.f;

    const float4* sW4  = (const float4*)sWr;
    const float4* sX4c = (const float4*)sX;

#pragma unroll 2
    for (int d4 = 0; d4 < DN / 4; d4++) {
        float4 wr[4];
#pragma unroll
        for (int dd = 0; dd < 4; dd++) wr[dd] = sW4[(d4 * 4 + dd) * 32 + l];
#pragma unroll
        for (int q = 0; q < 4; q++) {
            float4 xh = sX4c[(tb + q) * 64 + d4];
            float4 xt = sX4c[(tb + q) * 64 + 32 + d4];
            const float* xhp = &xh.x;
            const float* xtp = &xt.x;
#pragma unroll
            for (int dd = 0; dd < 4; dd++) {
                const float* wp = &wr[dd].x;
#pragma unroll
                for (int j = 0; j < 4; j++) {
                    acc[q][j]     = fmaf(xhp[dd], wp[j], acc[q][j]);
                    acc[q][4 + j] = fmaf(xtp[dd], wp[j], acc[q][4 + j]);
                }
            }
        }
    }

    // ---- conv + relu + fc epilogue (fc_w straight from global) ----
    float4 rr = ((const float4*)sRel)[l];
    const float* rrp = &rr.x;
    float part[4] = {0.f, 0.f, 0.f, 0.f};
    const float4* gF = (const float4*)fc_w;   // row c at index c*32 + l
    const float4* sCp4 = (const float4*)sCp;

#pragma unroll 2
    for (int c = 0; c < CN; c++) {
        float4 cp = sCp4[c];
        float4 fw = __ldg(&gF[c * 32 + l]);
        const float* fwp = &fw.x;
        float sj[4];
#pragma unroll
        for (int j = 0; j < 4; j++) sj[j] = fmaf(rrp[j], cp.y, cp.w);
#pragma unroll
        for (int q = 0; q < 4; q++) {
#pragma unroll
            for (int j = 0; j < 4; j++) {
                float g = fmaf(acc[q][j], cp.x, fmaf(acc[q][4 + j], cp.z, sj[j]));
                g = fmaxf(g, 0.f);
                part[q] = fmaf(g, fwp[j], part[q]);
            }
        }
    }

    const float fcb = __ldg(fc_b);
#pragma unroll
    for (int q = 0; q < 4; q++) {
        float v = part[q];
#pragma unroll
        for (int s = 16; s; s >>= 1) v += __shfl_xor_sync(0xffffffffu, v, s);
        if (l == 0 && tb + q < n) out[sTid[tb + q]] = v + fcb;
    }
}

// ---------------------------------------------------------------------------
extern "C" void kernel_launch(void* const* d_in, const int* in_sizes, int n_in,
                              void* d_out, int out_size)
{
    const int*   triples = (const int*)d_in[0];
    const float* ent_emb = (const float*)d_in[1];
    const float* rel_emb = (const float*)d_in[2];
    const float* rel_W   = (const float*)d_in[3];
    const float* conv_w  = (const float*)d_in[4];
    const float* conv_b  = (const float*)d_in[5];
    const float* fc_w    = (const float*)d_in[6];
    const float* fc_b    = (const float*)d_in[7];
    float* out = (float*)d_out;

    cudaFuncSetAttribute(k_main, cudaFuncAttributeMaxDynamicSharedMemorySize, SMEM_BYTES);

    k_hist<<<(BNUM + 255) / 256, 256>>>(triples);
    k_scan<<<1, 32>>>();
    k_scatter<<<BNUM / 512, 512>>>(triples);
    k_main<<<RNUM * KCH, NTHR, SMEM_BYTES>>>(triples, ent_emb, rel_emb, rel_W,
                                             conv_w, conv_b, fc_w, fc_b, out);
}

// round 11
// speedup vs baseline: 2.0128x; 1.2179x over previous
#include <cuda_runtime.h>
#include <cuda_bf16.h>
#include <cstdint>

// Problem constants
#define DN   128      // embedding dim
#define CN   50       // conv channels
#define RNUM 237      // relations
#define BNUM 16384    // triples
#define TB   64       // triple slots per CTA (MMA M = 128 = 64 h + 64 t)
#define NTHR 512      // 16 warps

// ---- device scratch ----
__device__ int g_count[RNUM];   // zero at module load; k_scan resets it each run
__device__ int g_start[RNUM];
__device__ int g_cnt[RNUM];
__device__ int g_cursor[RNUM];
__device__ int g_sorted[BNUM];

// ---------------------------------------------------------------------------
// Prep: hist -> scan(+reset) -> aggregated scatter  (proven)
// ---------------------------------------------------------------------------
__global__ void k_hist(const int* __restrict__ triples) {
    __shared__ int sh[RNUM];
    for (int i = threadIdx.x; i < RNUM; i += blockDim.x) sh[i] = 0;
    __syncthreads();
    int i = blockIdx.x * blockDim.x + threadIdx.x;
    if (i < BNUM) atomicAdd(&sh[triples[3 * i + 1]], 1);
    __syncthreads();
    for (int i2 = threadIdx.x; i2 < RNUM; i2 += blockDim.x) {
        int v = sh[i2];
        if (v) atomicAdd(&g_count[i2], v);
    }
}

__global__ void k_scan() {
    int l = threadIdx.x;
    int vals[8], cnts[8];
    int sum = 0;
#pragma unroll
    for (int j = 0; j < 8; j++) {
        int b = l * 8 + j;
        vals[j] = sum;
        cnts[j] = (b < RNUM) ? g_count[b] : 0;
        sum += cnts[j];
    }
    int x = sum;
#pragma unroll
    for (int sft = 1; sft < 32; sft <<= 1) {
        int y = __shfl_up_sync(0xffffffffu, x, sft);
        if (l >= sft) x += y;
    }
    int off = x - sum;
#pragma unroll
    for (int j = 0; j < 8; j++) {
        int b = l * 8 + j;
        if (b < RNUM) {
            int s = off + vals[j];
            g_start[b]  = s;
            g_cursor[b] = s;
            g_cnt[b]    = cnts[j];
            g_count[b]  = 0;
        }
    }
}

__global__ void k_scatter(const int* __restrict__ triples) {
    __shared__ int lcnt[RNUM];
    __shared__ int lcur[RNUM];
    const int tid = threadIdx.x;
    for (int i = tid; i < RNUM; i += 512) lcnt[i] = 0;
    __syncthreads();
    const int i = blockIdx.x * 512 + tid;
    const int r = triples[3 * i + 1];
    atomicAdd(&lcnt[r], 1);
    __syncthreads();
    for (int b = tid; b < RNUM; b += 512) {
        int c = lcnt[b];
        int base = c ? atomicAdd(&g_cursor[b], c) : 0;
        lcur[b] = base;
    }
    __syncthreads();
    int pos = atomicAdd(&lcur[r], 1);
    g_sorted[pos] = i;
}

// ---------------------------------------------------------------------------
// MMA helpers (generic PTX: ldmatrix + mma.sync bf16 — compiles at compute_103)
// ---------------------------------------------------------------------------
__device__ __forceinline__ uint32_t smem_u32(const void* p) {
    uint32_t a;
    asm("{ .reg .u64 t; cvta.to.shared.u64 t, %1; cvt.u32.u64 %0, t; }" : "=r"(a) : "l"(p));
    return a;
}
__device__ __forceinline__ void ldsm4(unsigned* f, uint32_t addr) {
    asm volatile("ldmatrix.sync.aligned.m8n8.x4.shared.b16 {%0,%1,%2,%3}, [%4];"
                 : "=r"(f[0]), "=r"(f[1]), "=r"(f[2]), "=r"(f[3]) : "r"(addr));
}
__device__ __forceinline__ void ldsm4t(unsigned* f, uint32_t addr) {
    asm volatile("ldmatrix.sync.aligned.m8n8.x4.trans.shared.b16 {%0,%1,%2,%3}, [%4];"
                 : "=r"(f[0]), "=r"(f[1]), "=r"(f[2]), "=r"(f[3]) : "r"(addr));
}
__device__ __forceinline__ void mma16816(float* c, const unsigned* a, unsigned b0, unsigned b1) {
    asm volatile(
        "mma.sync.aligned.m16n8k16.row.col.f32.bf16.bf16.f32 "
        "{%0,%1,%2,%3}, {%4,%5,%6,%7}, {%8,%9}, {%0,%1,%2,%3};"
        : "+f"(c[0]), "+f"(c[1]), "+f"(c[2]), "+f"(c[3])
        : "r"(a[0]), "r"(a[1]), "r"(a[2]), "r"(a[3]), "r"(b0), "r"(b1));
}

// f32 pair -> bf16x2 hi + bf16x2 lo (split precision)
__device__ __forceinline__ void cvt2(float a, float b, unsigned& hi, unsigned& lo) {
    __nv_bfloat16 ah = __float2bfloat16_rn(a);
    __nv_bfloat16 bh = __float2bfloat16_rn(b);
    float ar = a - __bfloat162float(ah);
    float br = b - __bfloat162float(bh);
    __nv_bfloat162 H; H.x = ah; H.y = bh;
    __nv_bfloat162 L; L.x = __float2bfloat16_rn(ar); L.y = __float2bfloat16_rn(br);
    hi = *reinterpret_cast<unsigned*>(&H);
    lo = *reinterpret_cast<unsigned*>(&L);
}

// smem layout (bytes). bf16 tiles: 128 rows x 128 cols, row stride 272B
#define TSTR    272
#define TILE_B  (128 * TSTR)       // 34816
#define OFF_AH  0
#define OFF_AL  (TILE_B)           // 34816
#define OFF_BH  (2 * TILE_B)       // 69632
#define OFF_BL  (3 * TILE_B)       // 104448
#define OFF_D   0                  // fp32 128 x 132 (67584 B) — overlays A after MMA
#define SD_STRIDE 132
#define OFF_REL (4 * TILE_B)       // 139264
#define OFF_CP  (OFF_REL + 512)    // 139776
#define OFF_TID (OFF_CP + 800)     // 140576
#define SMEM_BYTES (OFF_TID + 256) // 140832

__global__ __launch_bounds__(NTHR, 1)
void k_main(const int* __restrict__ triples,
            const float* __restrict__ ent_emb,
            const float* __restrict__ rel_emb,
            const float* __restrict__ rel_W,
            const float* __restrict__ conv_w,
            const float* __restrict__ conv_b,
            const float* __restrict__ fc_w,
            const float* __restrict__ fc_b,
            float* __restrict__ out)
{
    const int r     = blockIdx.x >> 1;
    const int chunk = blockIdx.x & 1;

    const int cnt   = g_cnt[r];
    const int nhalf = (cnt + 1) >> 1;
    const int off0  = chunk ? nhalf : 0;
    const int n     = chunk ? min(TB, cnt - nhalf) : min(TB, nhalf);
    if (n <= 0) return;
    const int gbase = g_start[r] + off0;

    extern __shared__ char smc[];
    float* sD   = (float*)(smc + OFF_D);
    float* sRel = (float*)(smc + OFF_REL);
    float* sCp  = (float*)(smc + OFF_CP);
    int*   sTid = (int*)(smc + OFF_TID);

    const int tid  = threadIdx.x;
    const int wid  = tid >> 5;
    const int lane = tid & 31;
    const uint32_t sbase = smem_u32(smc);

    // ---- stage Wr natural [d][e] as bf16 hi/lo (coalesced, conflict-free) ----
    {
        const int e2 = (tid & 63) * 2;          // e pair
        const int dg = tid >> 6;                // 0..7 -> 16 d-rows each
        const float* Wb = rel_W + (size_t)r * DN * DN;
#pragma unroll 4
        for (int dd = 0; dd < 16; dd++) {
            int d = dg * 16 + dd;
            float2 v = *(const float2*)(Wb + (size_t)d * DN + e2);
            unsigned H, L;
            cvt2(v.x, v.y, H, L);
            *(unsigned*)(smc + OFF_BH + d * TSTR + e2 * 2) = H;
            *(unsigned*)(smc + OFF_BL + d * TSTR + e2 * 2) = L;
        }
    }

    // ---- stage entities [slot][d] bf16 hi/lo: rows 0..63 = h, 64..127 = t ----
    {
        const int rp = tid >> 2;                 // row 0..127
        const int q4 = tid & 3;                  // col quarter (32 cols)
        const int c0 = q4 * 32;
        const int slot = rp & 63;
        const bool isH = rp < 64;
        if (slot < n) {
            int i = g_sorted[gbase + slot];
            if (isH && q4 == 0) sTid[slot] = i;
            int ent = isH ? triples[3 * i] : triples[3 * i + 2];
            const float4* ev = (const float4*)(ent_emb + (size_t)ent * DN);
#pragma unroll
            for (int b = 0; b < 4; b++) {
                float4 u = ev[(c0 >> 2) + 2 * b];
                float4 v = ev[(c0 >> 2) + 2 * b + 1];
                unsigned h0,l0,h1,l1,h2,l2,h3,l3;
                cvt2(u.x, u.y, h0, l0); cvt2(u.z, u.w, h1, l1);
                cvt2(v.x, v.y, h2, l2); cvt2(v.z, v.w, h3, l3);
                uint4 H = make_uint4(h0, h1, h2, h3);
                uint4 L = make_uint4(l0, l1, l2, l3);
                int o = rp * TSTR + (c0 + 8 * b) * 2;
                *(uint4*)(smc + OFF_AH + o) = H;
                *(uint4*)(smc + OFF_AL + o) = L;
            }
        } else {
            uint4 Z = make_uint4(0, 0, 0, 0);
#pragma unroll
            for (int b = 0; b < 4; b++) {
                int o = rp * TSTR + (c0 + 8 * b) * 2;
                *(uint4*)(smc + OFF_AH + o) = Z;
                *(uint4*)(smc + OFF_AL + o) = Z;
            }
        }
    }

    // ---- stage rel_emb + packed conv params ----
    if (tid < 32) ((float4*)sRel)[tid] = ((const float4*)(rel_emb + (size_t)r * DN))[tid];
    if (tid < CN) {
        float4 cp;
        cp.x = conv_w[3 * tid + 0];
        cp.y = conv_w[3 * tid + 1];
        cp.z = conv_w[3 * tid + 2];
        cp.w = conv_b[tid];
        ((float4*)sCp)[tid] = cp;
    }
    __syncthreads();

    // ---- MMA: warp w -> m-tile (w&7)*16, n-half (w>>3)*64 ----
    // D = Ah*Bh + Al*Bh + Ah*Bl
    const int m0 = (wid & 7) * 16;
    const int nb = (wid >> 3) * 64;

    float acc[8][4];
#pragma unroll
    for (int tI = 0; tI < 8; tI++)
#pragma unroll
        for (int j = 0; j < 4; j++) acc[tI][j] = 0.f;

    // A frag address: lanes 0-7 rows m0+0..7 (off 0), 8-15 rows +8 (off 0),
    //                 16-23 rows 0..7 (off 16B), 24-31 rows +8 (off 16B)
    const uint32_t aRow = m0 + ((lane >> 3) & 1) * 8 + (lane & 7);
    const uint32_t aCol16 = (lane >> 4) << 4;
    // B (trans) addr: matrices are [d][e] tiles; lanes 0-7 d-rows k0..+7 e=n0,
    //                 8-15 d+8 e=n0, 16-23 d..+7 e=n0+8, 24-31 d+8 e=n0+8
    const uint32_t bDrow = ((lane >> 3) & 1) * 8 + (lane & 7);
    const uint32_t bEoff = ((lane >> 4) << 3) * 2;

#pragma unroll
    for (int k0 = 0; k0 < 8; k0++) {
        unsigned ah[4], al[4];
        {
            uint32_t ad = sbase + aRow * TSTR + k0 * 32 + aCol16;
            ldsm4(ah, ad + OFF_AH);
            ldsm4(al, ad + OFF_AL);
        }
#pragma unroll
        for (int np = 0; np < 4; np++) {
            const int n0 = nb + np * 16;
            unsigned bh[4], bl[4];
            uint32_t bd = sbase + (k0 * 16 + bDrow) * TSTR + n0 * 2 + bEoff;
            ldsm4t(bh, bd + OFF_BH);
            ldsm4t(bl, bd + OFF_BL);
            float* c0 = acc[np * 2];
            float* c1 = acc[np * 2 + 1];
            mma16816(c0, ah, bh[0], bh[1]);
            mma16816(c1, ah, bh[2], bh[3]);
            mma16816(c0, al, bh[0], bh[1]);
            mma16816(c1, al, bh[2], bh[3]);
            mma16816(c0, ah, bl[0], bl[1]);
            mma16816(c1, ah, bl[2], bl[3]);
        }
    }
    __syncthreads();   // all warps done reading A/B before sD overlays them

    // ---- store accumulators to sD[row][col] (stride 132) ----
    {
        const int g  = lane >> 2;
        const int tg = lane & 3;
#pragma unroll
        for (int np = 0; np < 4; np++) {
#pragma unroll
            for (int t = 0; t < 2; t++) {
                const float* c = acc[np * 2 + t];
                int col = nb + np * 16 + t * 8 + 2 * tg;
                *(float2*)(sD + (m0 + g) * SD_STRIDE + col)     = make_float2(c[0], c[1]);
                *(float2*)(sD + (m0 + 8 + g) * SD_STRIDE + col) = make_float2(c[2], c[3]);
            }
        }
    }
    __syncthreads();

    // ---- epilogue: warp w -> slots 4w..4w+3; lane l -> cols 4l..4l+3 ----
    const int tb = wid * 4;
    if (tb < n) {
        float4 ph4[4], pt4[4];
#pragma unroll
        for (int q = 0; q < 4; q++) {
            int s = tb + q;
            ph4[q] = *(const float4*)(sD + s * SD_STRIDE + 4 * lane);
            pt4[q] = *(const float4*)(sD + (64 + s) * SD_STRIDE + 4 * lane);
        }
        float4 rr = ((const float4*)sRel)[lane];
        const float* rrp = &rr.x;
        float part[4] = {0.f, 0.f, 0.f, 0.f};
        const float4* gF = (const float4*)fc_w;
        const float4* sCp4 = (const float4*)sCp;

#pragma unroll 2
        for (int c = 0; c < CN; c++) {
            float4 cp = sCp4[c];
            float4 fw = __ldg(&gF[c * 32 + lane]);
            const float* fwp = &fw.x;
            float sj[4];
#pragma unroll
            for (int j = 0; j < 4; j++) sj[j] = fmaf(rrp[j], cp.y, cp.w);
#pragma unroll
            for (int q = 0; q < 4; q++) {
                const float* php = &ph4[q].x;
                const float* ptp = &pt4[q].x;
#pragma unroll
                for (int j = 0; j < 4; j++) {
                    float g = fmaf(php[j], cp.x, fmaf(ptp[j], cp.z, sj[j]));
                    g = fmaxf(g, 0.f);
                    part[q] = fmaf(g, fwp[j], part[q]);
                }
            }
        }

        const float fcb = __ldg(fc_b);
#pragma unroll
        for (int q = 0; q < 4; q++) {
            float v = part[q];
#pragma unroll
            for (int s = 16; s; s >>= 1) v += __shfl_xor_sync(0xffffffffu, v, s);
            if (lane == 0 && tb + q < n) out[sTid[tb + q]] = v + fcb;
        }
    }
}

// ---------------------------------------------------------------------------
extern "C" void kernel_launch(void* const* d_in, const int* in_sizes, int n_in,
                              void* d_out, int out_size)
{
    const int*   triples = (const int*)d_in[0];
    const float* ent_emb = (const float*)d_in[1];
    const float* rel_emb = (const float*)d_in[2];
    const float* rel_W   = (const float*)d_in[3];
    const float* conv_w  = (const float*)d_in[4];
    const float* conv_b  = (const float*)d_in[5];
    const float* fc_w    = (const float*)d_in[6];
    const float* fc_b    = (const float*)d_in[7];
    float* out = (float*)d_out;

    cudaFuncSetAttribute(k_main, cudaFuncAttributeMaxDynamicSharedMemorySize, SMEM_BYTES);

    k_hist<<<(BNUM + 255) / 256, 256>>>(triples);
    k_scan<<<1, 32>>>();
    k_scatter<<<BNUM / 512, 512>>>(triples);
    k_main<<<RNUM * 2, NTHR, SMEM_BYTES>>>(triples, ent_emb, rel_emb, rel_W,
                                           conv_w, conv_b, fc_w, fc_b, out);
}